// round 10
// baseline (speedup 1.0000x reference)
#include <cuda_runtime.h>
#include <cuda_bf16.h>
#include <cstdint>

#define Bsz 8
#define Ssz 1024
#define Esz 768
#define Hsz 12
#define Dsz 64
#define Msz (Bsz*Ssz)   // 8192

// ---------------- scratch (device globals; referenced ONLY in device code) ----------------
__device__ float g_q[Bsz*Hsz*Ssz*Dsz];     // rounded + 0.125-scaled q
__device__ float g_k[Bsz*Hsz*Ssz*Dsz];     // rounded k
__device__ float g_v[Bsz*Hsz*Ssz*Dsz];     // rounded v
__device__ float g_attn[Bsz*Ssz*Esz];      // rounded attention output
__device__ float g_xr[(size_t)Msz*Esz];    // rounded X
__device__ float g_wT[(size_t)(3*Esz)*Esz];// rounded W^T [2304][768], q rows pre-scaled
__device__ float g_woT[(size_t)Esz*Esz];   // rounded Wo^T [768][768]

// ---------------- helpers ----------------
__device__ __forceinline__ unsigned f2tf(float f) {
    unsigned u;
    asm("cvt.rna.tf32.f32 %0, %1;" : "=r"(u) : "f"(f));
    return u;
}
__device__ __forceinline__ float roundtf(float f) { return __uint_as_float(f2tf(f)); }
__device__ __forceinline__ void mma_tf32(float* c, const unsigned* a, unsigned b0, unsigned b1) {
    asm volatile(
        "mma.sync.aligned.m16n8k8.row.col.f32.tf32.tf32.f32 "
        "{%0,%1,%2,%3}, {%4,%5,%6,%7}, {%8,%9}, {%0,%1,%2,%3};"
        : "+f"(c[0]), "+f"(c[1]), "+f"(c[2]), "+f"(c[3])
        : "r"(a[0]), "r"(a[1]), "r"(a[2]), "r"(a[3]), "r"(b0), "r"(b1));
}
__device__ __forceinline__ void ldsm_x4(unsigned& r0, unsigned& r1, unsigned& r2, unsigned& r3,
                                        unsigned saddr) {
    asm volatile("ldmatrix.sync.aligned.m8n8.x4.shared.b16 {%0,%1,%2,%3}, [%4];"
        : "=r"(r0), "=r"(r1), "=r"(r2), "=r"(r3) : "r"(saddr));
}
__device__ __forceinline__ unsigned smem_u32(const void* p) {
    unsigned a;
    asm("{ .reg .u64 t; cvta.to.shared.u64 t, %1; cvt.u32.u64 %0, t; }" : "=r"(a) : "l"(p));
    return a;
}

// ============================================================================
// Conversion kernels (one-time, tiny). Destinations are device globals
// referenced IN DEVICE CODE (the R8/R9 bug was passing them from host).
// ============================================================================
__global__ __launch_bounds__(256) void conv_round(const float* __restrict__ src)
{
    int i = (blockIdx.x * 256 + threadIdx.x) * 4;
    float4 v = *(const float4*)(src + i);
    v.x = roundtf(v.x); v.y = roundtf(v.y); v.z = roundtf(v.z); v.w = roundtf(v.w);
    *(float4*)(g_xr + i) = v;
}

// W^T row n (0..2303): which = n/768, head = (n%768)>>6, d = n&63; q rows scaled 0.125
__global__ __launch_bounds__(128) void conv_wqkvT(const float* __restrict__ Wq,
                                                  const float* __restrict__ Wk,
                                                  const float* __restrict__ Wv)
{
    int n = blockIdx.x;
    int which = n / Esz, rem = n % Esz, h = rem >> 6, d = rem & 63;
    const float* W = (which == 0) ? Wq : (which == 1 ? Wk : Wv);
    const float sc = (which == 0) ? 0.125f : 1.0f;
    const float* col = W + (size_t)h * Esz * Dsz + d;
    float* row = g_wT + (size_t)n * Esz;
    for (int e = threadIdx.x; e < Esz; e += 128)
        row[e] = roundtf(col[(size_t)e * Dsz] * sc);
}

__global__ __launch_bounds__(128) void conv_woT(const float* __restrict__ Wo)
{
    int n = blockIdx.x;
    float* row = g_woT + (size_t)n * Esz;
    for (int e = threadIdx.x; e < Esz; e += 128)
        row[e] = roundtf(Wo[(size_t)e * Esz + n]);
}

// ============================================================================
// tf32 GEMM, register-staged double buffer (R6-proven skeleton).
// Tile 128M x 128N, Kc=16, 8 warps (2m x 4n), warp 64x32, all frags LDSM.
// Inputs selected from device globals by `mode`:
//   mode 0: A=g_xr,  Bt=g_wT  -> qkv (per-head bias, rounded scatter, q pre-scaled)
//   mode 1: A=g_attn, Bt=g_woT -> oproj (bias bo, fp32 row-major Out)
// ============================================================================
#define AST 20
#define BKST 20
#define CHUNKS 48

__global__ __launch_bounds__(256, 2) void gemm_rs(
    const float* __restrict__ b0p, const float* __restrict__ b1p,
    const float* __restrict__ b2p,
    float* __restrict__ Out, int mode)
{
    __shared__ unsigned As[2][128 * AST];   // 20.5 KB
    __shared__ unsigned Bs[2][128 * BKST];  // 20.5 KB

    const float* A  = (mode == 0) ? g_xr  : g_attn;
    const float* Bt = (mode == 0) ? g_wT  : g_woT;

    const int t    = threadIdx.x;
    const int warp = t >> 5;
    const int lane = t & 31;
    const int g    = lane >> 2;
    const int tg   = lane & 3;
    const int wm   = (warp & 1) * 64;
    const int wn   = (warp >> 1) * 32;
    const int n0   = blockIdx.x * 128;
    const int m0   = blockIdx.y * 128;

    const unsigned a_lane = (((lane >> 3) & 1) * 8 + (lane & 7)) * AST + (lane >> 4) * 4;
    const unsigned b_lane = (lane & 7) * BKST + (lane >> 3) * 4;
    const unsigned as_base0 = smem_u32(&As[0][0]);
    const unsigned as_base1 = smem_u32(&As[1][0]);
    const unsigned bs_base0 = smem_u32(&Bs[0][0]);
    const unsigned bs_base1 = smem_u32(&Bs[1][0]);

    // global mapping: thread covers rows arow and arow+64, 16B segment acol
    const int arow = t >> 2;
    const int acol = (t & 3) << 2;          // word offset 0/4/8/12
    const float* Ag = A  + (size_t)(m0 + arow) * Esz + acol;
    const float* Bg = Bt + (size_t)(n0 + arow) * Esz + acol;

    // prologue: chunk 0
    uint4 ra0 = *(const uint4*)(Ag);
    uint4 ra1 = *(const uint4*)(Ag + (size_t)64 * Esz);
    uint4 rb0 = *(const uint4*)(Bg);
    uint4 rb1 = *(const uint4*)(Bg + (size_t)64 * Esz);
    *(uint4*)&As[0][arow * AST + acol]        = ra0;
    *(uint4*)&As[0][(arow + 64) * AST + acol] = ra1;
    *(uint4*)&Bs[0][arow * BKST + acol]        = rb0;
    *(uint4*)&Bs[0][(arow + 64) * BKST + acol] = rb1;
    __syncthreads();

    float acc[4][4][4];
    #pragma unroll
    for (int mi = 0; mi < 4; mi++)
        #pragma unroll
        for (int ni = 0; ni < 4; ni++)
            #pragma unroll
            for (int j = 0; j < 4; j++) acc[mi][ni][j] = 0.f;

    for (int i = 0; i < CHUNKS; i++) {
        const int buf = i & 1;
        const unsigned as_base = buf ? as_base1 : as_base0;
        const unsigned bs_base = buf ? bs_base1 : bs_base0;
        const bool more = (i + 1) < CHUNKS;
        if (more) {
            const int c0 = (i + 1) * 16;
            ra0 = *(const uint4*)(Ag + c0);
            ra1 = *(const uint4*)(Ag + (size_t)64 * Esz + c0);
            rb0 = *(const uint4*)(Bg + c0);
            rb1 = *(const uint4*)(Bg + (size_t)64 * Esz + c0);
        }

        // B fragments for the whole chunk (both k-steps)
        unsigned bf[4][4];
        #pragma unroll
        for (int ni = 0; ni < 4; ni++)
            ldsm_x4(bf[ni][0], bf[ni][1], bf[ni][2], bf[ni][3],
                    bs_base + 4 * ((wn + ni * 8) * BKST + b_lane));
        #pragma unroll
        for (int ks = 0; ks < 2; ks++) {
            unsigned a[4][4];
            #pragma unroll
            for (int mi = 0; mi < 4; mi++)
                ldsm_x4(a[mi][0], a[mi][1], a[mi][2], a[mi][3],
                        as_base + 4 * ((wm + mi * 16) * AST + ks * 8 + a_lane));
            #pragma unroll
            for (int ni = 0; ni < 4; ni++)
                #pragma unroll
                for (int mi = 0; mi < 4; mi++)
                    mma_tf32(acc[mi][ni], a[mi], bf[ni][2 * ks], bf[ni][2 * ks + 1]);
        }

        if (more) {
            const int nb = buf ^ 1;
            *(uint4*)&As[nb][arow * AST + acol]        = ra0;
            *(uint4*)&As[nb][(arow + 64) * AST + acol] = ra1;
            *(uint4*)&Bs[nb][arow * BKST + acol]        = rb0;
            *(uint4*)&Bs[nb][(arow + 64) * BKST + acol] = rb1;
        }
        __syncthreads();
    }

    // ---- epilogue ----
    if (mode == 0) {
        const int which = n0 / Esz;
        const float* bias = (which == 0) ? b0p : (which == 1 ? b1p : b2p);
        float* OUTsel     = (which == 0) ? g_q : (which == 1 ? g_k : g_v);
        const float bsc   = (which == 0) ? 0.125f : 1.0f;
        const int nrel = n0 % Esz;
        #pragma unroll
        for (int mi = 0; mi < 4; mi++) {
            const int row_lo = m0 + wm + mi * 16 + g;
            const int row_hi = row_lo + 8;
            const int blo = row_lo >> 10, slo = row_lo & 1023;
            const int bhi = row_hi >> 10, shi = row_hi & 1023;
            #pragma unroll
            for (int ni = 0; ni < 4; ni++) {
                const int nc = nrel + wn + ni * 8 + 2 * tg;
                const int head = nc >> 6, d = nc & 63;
                float2 bb = *(const float2*)(bias + head * Dsz + d);
                bb.x *= bsc; bb.y *= bsc;
                float* olo = OUTsel + ((((size_t)blo * Hsz + head) << 10) + slo) * Dsz + d;
                float* ohi = OUTsel + ((((size_t)bhi * Hsz + head) << 10) + shi) * Dsz + d;
                float2 wlo, whi;
                wlo.x = roundtf(acc[mi][ni][0] + bb.x);
                wlo.y = roundtf(acc[mi][ni][1] + bb.y);
                whi.x = roundtf(acc[mi][ni][2] + bb.x);
                whi.y = roundtf(acc[mi][ni][3] + bb.y);
                *(float2*)olo = wlo;
                *(float2*)ohi = whi;
            }
        }
    } else {
        #pragma unroll
        for (int mi = 0; mi < 4; mi++) {
            const int row_lo = m0 + wm + mi * 16 + g;
            float* olo = Out + (size_t)row_lo * Esz + n0;
            float* ohi = olo + (size_t)8 * Esz;
            #pragma unroll
            for (int ni = 0; ni < 4; ni++) {
                const int col = wn + ni * 8 + 2 * tg;
                float2 bb = *(const float2*)(b0p + n0 + col);
                float2 wlo, whi;
                wlo.x = acc[mi][ni][0] + bb.x; wlo.y = acc[mi][ni][1] + bb.y;
                whi.x = acc[mi][ni][2] + bb.x; whi.y = acc[mi][ni][3] + bb.y;
                *(float2*)(olo + col) = wlo;
                *(float2*)(ohi + col) = whi;
            }
        }
    }
}

// ============================================================================
// Flash attention (tf32 mma.sync) — R5-proven structure; inputs pre-rounded
// so tile loads are raw copies. Output stored tf32-rounded for oproj.
// ============================================================================
#define KST 68
#define VST 72

__global__ __launch_bounds__(128) void attn_kernel()
{
    __shared__ unsigned Ksm[64 * KST];     // K tile [n][k] -> reused as P [m][k]
    __shared__ unsigned Vsm[64 * VST];     // V tile [k][d]

    const int bh = blockIdx.y;
    const int b = bh / Hsz, h = bh % Hsz;
    const int tid  = threadIdx.x;
    const int warp = tid >> 5;
    const int lane = tid & 31;
    const int g  = lane >> 2;
    const int tg = lane & 3;
    const int r0 = warp * 16;

    const unsigned ks_base = smem_u32(Ksm);
    const unsigned kf_lane = (lane & 7) * KST + (lane >> 3) * 4;
    const unsigned pf_lane = (((lane >> 3) & 1) * 8 + (lane & 7)) * KST + (lane >> 4) * 4;

    // ---- stage Q (already scaled+rounded) into Ksm, extract A-frags ----
    {
        const uint4* Qg = (const uint4*)(g_q + ((size_t)bh * Ssz + blockIdx.x * 64) * Dsz);
        #pragma unroll
        for (int i = 0; i < 8; i++) {
            int idx = i * 128 + tid;
            int row = idx >> 4, c = (idx & 15) << 2;
            *(uint4*)&Ksm[row * KST + c] = Qg[idx];
        }
    }
    __syncthreads();

    unsigned qa[8][4];
    #pragma unroll
    for (int kk = 0; kk < 8; kk++) {
        unsigned addr = ks_base + 4 * (r0 * KST + kk * 8 + pf_lane);
        ldsm_x4(qa[kk][0], qa[kk][1], qa[kk][2], qa[kk][3], addr);
    }
    __syncthreads();

    float o[8][4];
    #pragma unroll
    for (int nf = 0; nf < 8; nf++)
        #pragma unroll
        for (int j = 0; j < 4; j++) o[nf][j] = 0.f;
    float m_lo = -1e30f, m_hi = -1e30f, l_lo = 0.f, l_hi = 0.f;

    const uint4* Kg0 = (const uint4*)(g_k + (size_t)bh * (Ssz * Dsz));
    const uint4* Vg0 = (const uint4*)(g_v + (size_t)bh * (Ssz * Dsz));

    for (int kb = 0; kb < Ssz / 64; kb++) {
        const uint4* Kg = Kg0 + kb * 1024;
        const uint4* Vg = Vg0 + kb * 1024;
        #pragma unroll
        for (int i = 0; i < 8; i++) {
            int idx = i * 128 + tid;
            int row = idx >> 4, c = (idx & 15) << 2;
            *(uint4*)&Ksm[row * KST + c] = Kg[idx];
            *(uint4*)&Vsm[row * VST + c] = Vg[idx];
        }
        __syncthreads();

        float s[8][4];
        #pragma unroll
        for (int nf = 0; nf < 8; nf++)
            #pragma unroll
            for (int j = 0; j < 4; j++) s[nf][j] = 0.f;

        #pragma unroll
        for (int nf = 0; nf < 8; nf++) {
            #pragma unroll
            for (int p = 0; p < 4; p++) {
                unsigned kb0, kb1, kb2, kb3;
                unsigned addr = ks_base + 4 * ((nf * 8) * KST + p * 16 + kf_lane);
                ldsm_x4(kb0, kb1, kb2, kb3, addr);
                mma_tf32(s[nf], qa[2 * p],     kb0, kb1);
                mma_tf32(s[nf], qa[2 * p + 1], kb2, kb3);
            }
        }
        __syncthreads();

        float tmax_lo = -1e30f, tmax_hi = -1e30f;
        #pragma unroll
        for (int nf = 0; nf < 8; nf++) {
            tmax_lo = fmaxf(tmax_lo, fmaxf(s[nf][0], s[nf][1]));
            tmax_hi = fmaxf(tmax_hi, fmaxf(s[nf][2], s[nf][3]));
        }
        tmax_lo = fmaxf(tmax_lo, __shfl_xor_sync(0xffffffffu, tmax_lo, 1));
        tmax_lo = fmaxf(tmax_lo, __shfl_xor_sync(0xffffffffu, tmax_lo, 2));
        tmax_hi = fmaxf(tmax_hi, __shfl_xor_sync(0xffffffffu, tmax_hi, 1));
        tmax_hi = fmaxf(tmax_hi, __shfl_xor_sync(0xffffffffu, tmax_hi, 2));

        float mn_lo = fmaxf(m_lo, tmax_lo);
        float mn_hi = fmaxf(m_hi, tmax_hi);
        float a_lo = __expf(m_lo - mn_lo);
        float a_hi = __expf(m_hi - mn_hi);

        float sum_lo = 0.f, sum_hi = 0.f;
        #pragma unroll
        for (int nf = 0; nf < 8; nf++) {
            float p0 = __expf(s[nf][0] - mn_lo);
            float p1 = __expf(s[nf][1] - mn_lo);
            float p2 = __expf(s[nf][2] - mn_hi);
            float p3 = __expf(s[nf][3] - mn_hi);
            sum_lo += p0 + p1;
            sum_hi += p2 + p3;
            uint2 plo, phi;
            plo.x = f2tf(p0); plo.y = f2tf(p1);
            phi.x = f2tf(p2); phi.y = f2tf(p3);
            *(uint2*)&Ksm[(r0 + g) * KST + nf * 8 + 2 * tg]     = plo;
            *(uint2*)&Ksm[(r0 + g + 8) * KST + nf * 8 + 2 * tg] = phi;
            o[nf][0] *= a_lo; o[nf][1] *= a_lo;
            o[nf][2] *= a_hi; o[nf][3] *= a_hi;
        }
        sum_lo += __shfl_xor_sync(0xffffffffu, sum_lo, 1);
        sum_lo += __shfl_xor_sync(0xffffffffu, sum_lo, 2);
        sum_hi += __shfl_xor_sync(0xffffffffu, sum_hi, 1);
        sum_hi += __shfl_xor_sync(0xffffffffu, sum_hi, 2);
        l_lo = l_lo * a_lo + sum_lo;
        l_hi = l_hi * a_hi + sum_hi;
        m_lo = mn_lo; m_hi = mn_hi;
        __syncwarp();                      // P visible within warp

        #pragma unroll
        for (int kk = 0; kk < 8; kk++) {
            unsigned pa[4];
            unsigned addr = ks_base + 4 * (r0 * KST + kk * 8 + pf_lane);
            ldsm_x4(pa[0], pa[1], pa[2], pa[3], addr);
            #pragma unroll
            for (int nf = 0; nf < 8; nf++) {
                unsigned b0 = Vsm[(kk * 8 + tg) * VST + nf * 8 + g];
                unsigned b1 = Vsm[(kk * 8 + tg + 4) * VST + nf * 8 + g];
                mma_tf32(o[nf], pa, b0, b1);
            }
        }
        __syncthreads();
    }

    float inv_lo = 1.f / l_lo;
    float inv_hi = 1.f / l_hi;
    const int qrow_lo = blockIdx.x * 64 + r0 + g;
    float* out_lo = g_attn + ((size_t)b * Ssz + qrow_lo) * Esz + h * Dsz;
    float* out_hi = out_lo + 8 * Esz;
    #pragma unroll
    for (int nf = 0; nf < 8; nf++) {
        int col = nf * 8 + 2 * tg;
        float2 wlo, whi;
        wlo.x = roundtf(o[nf][0] * inv_lo); wlo.y = roundtf(o[nf][1] * inv_lo);
        whi.x = roundtf(o[nf][2] * inv_hi); whi.y = roundtf(o[nf][3] * inv_hi);
        *(float2*)(out_lo + col) = wlo;
        *(float2*)(out_hi + col) = whi;
    }
}

// ---------------- launch ----------------
extern "C" void kernel_launch(void* const* d_in, const int* in_sizes, int n_in,
                              void* d_out, int out_size)
{
    const float* X  = (const float*)d_in[0];
    const float* Wq = (const float*)d_in[1];
    const float* bq = (const float*)d_in[2];
    const float* Wk = (const float*)d_in[3];
    const float* bk = (const float*)d_in[4];
    const float* Wv = (const float*)d_in[5];
    const float* bv = (const float*)d_in[6];
    const float* Wo = (const float*)d_in[7];
    const float* bo = (const float*)d_in[8];
    float* out = (float*)d_out;

    // one-time rounding / layout conversions (write device globals in device code)
    conv_round<<<(Msz * Esz) / (256 * 4), 256>>>(X);
    conv_wqkvT<<<3 * Esz, 128>>>(Wq, Wk, Wv);
    conv_woT<<<Esz, 128>>>(Wo);

    // QKV projection (tf32 mma, register-staged double buffer)
    gemm_rs<<<dim3(18, 64), 256>>>(bq, bk, bv, nullptr, 0);

    // attention
    attn_kernel<<<dim3(Ssz / 64, Bsz * Hsz), 128>>>();

    // output projection
    gemm_rs<<<dim3(6, 64), 256>>>(bo, nullptr, nullptr, out, 1);
}

// round 11
// speedup vs baseline: 1.0616x; 1.0616x over previous
#include <cuda_runtime.h>
#include <cuda_bf16.h>
#include <cstdint>

#define Bsz 8
#define Ssz 1024
#define Esz 768
#define Hsz 12
#define Dsz 64
#define Msz (Bsz*Ssz)   // 8192

// ---------------- scratch (device globals; referenced ONLY in device code) ----------------
__device__ float g_q[Bsz*Hsz*Ssz*Dsz];     // rounded + 0.125-scaled q
__device__ float g_k[Bsz*Hsz*Ssz*Dsz];     // rounded k
__device__ float g_v[Bsz*Hsz*Ssz*Dsz];     // rounded v
__device__ float g_attn[Bsz*Ssz*Esz];      // rounded attention output
__device__ float g_xr[(size_t)Msz*Esz];    // rounded X
__device__ float g_wT[(size_t)(3*Esz)*Esz];// rounded W^T [2304][768], q rows pre-scaled
__device__ float g_woT[(size_t)Esz*Esz];   // rounded Wo^T [768][768]

// ---------------- helpers ----------------
__device__ __forceinline__ unsigned f2tf(float f) {
    unsigned u;
    asm("cvt.rna.tf32.f32 %0, %1;" : "=r"(u) : "f"(f));
    return u;
}
__device__ __forceinline__ float roundtf(float f) { return __uint_as_float(f2tf(f)); }
__device__ __forceinline__ void mma_tf32(float* c, const unsigned* a, unsigned b0, unsigned b1) {
    asm volatile(
        "mma.sync.aligned.m16n8k8.row.col.f32.tf32.tf32.f32 "
        "{%0,%1,%2,%3}, {%4,%5,%6,%7}, {%8,%9}, {%0,%1,%2,%3};"
        : "+f"(c[0]), "+f"(c[1]), "+f"(c[2]), "+f"(c[3])
        : "r"(a[0]), "r"(a[1]), "r"(a[2]), "r"(a[3]), "r"(b0), "r"(b1));
}
__device__ __forceinline__ void ldsm_x4(unsigned& r0, unsigned& r1, unsigned& r2, unsigned& r3,
                                        unsigned saddr) {
    asm volatile("ldmatrix.sync.aligned.m8n8.x4.shared.b16 {%0,%1,%2,%3}, [%4];"
        : "=r"(r0), "=r"(r1), "=r"(r2), "=r"(r3) : "r"(saddr));
}
__device__ __forceinline__ unsigned smem_u32(const void* p) {
    unsigned a;
    asm("{ .reg .u64 t; cvta.to.shared.u64 t, %1; cvt.u32.u64 %0, t; }" : "=r"(a) : "l"(p));
    return a;
}
__device__ __forceinline__ void cp16(unsigned dst, const float* src) {
    asm volatile("cp.async.cg.shared.global [%0], [%1], 16;" :: "r"(dst), "l"(src));
}
#define CP_COMMIT()  asm volatile("cp.async.commit_group;" ::: "memory")
#define CP_WAIT1()   asm volatile("cp.async.wait_group 1;" ::: "memory")

// ============================================================================
// Conversion kernels (one-time, tiny). Write device globals from device code.
// ============================================================================
__global__ __launch_bounds__(256) void conv_round(const float* __restrict__ src)
{
    int i = (blockIdx.x * 256 + threadIdx.x) * 4;
    float4 v = *(const float4*)(src + i);
    v.x = roundtf(v.x); v.y = roundtf(v.y); v.z = roundtf(v.z); v.w = roundtf(v.w);
    *(float4*)(g_xr + i) = v;
}

__global__ __launch_bounds__(128) void conv_wqkvT(const float* __restrict__ Wq,
                                                  const float* __restrict__ Wk,
                                                  const float* __restrict__ Wv)
{
    int n = blockIdx.x;
    int which = n / Esz, rem = n % Esz, h = rem >> 6, d = rem & 63;
    const float* W = (which == 0) ? Wq : (which == 1 ? Wk : Wv);
    const float sc = (which == 0) ? 0.125f : 1.0f;
    const float* col = W + (size_t)h * Esz * Dsz + d;
    float* row = g_wT + (size_t)n * Esz;
    for (int e = threadIdx.x; e < Esz; e += 128)
        row[e] = roundtf(col[(size_t)e * Dsz] * sc);
}

__global__ __launch_bounds__(128) void conv_woT(const float* __restrict__ Wo)
{
    int n = blockIdx.x;
    float* row = g_woT + (size_t)n * Esz;
    for (int e = threadIdx.x; e < Esz; e += 128)
        row[e] = roundtf(Wo[(size_t)e * Esz + n]);
}

// ============================================================================
// tf32 GEMM, 3-stage cp.async pipeline. Tile 128M x 128N, Kc=16, 8 warps.
// Scratch selected in-kernel by mode (R8/R9 lesson: never pass device globals
// from host).
//   mode 0: A=g_xr,   Bt=g_wT   -> qkv epilogue
//   mode 1: A=g_attn, Bt=g_woT  -> oproj epilogue
// ============================================================================
#define AST 20
#define BKST 20
#define STG_WORDS (128*AST + 128*BKST)   // 5120
#define STG_BYTES (STG_WORDS*4)          // 20480
#define GSMEM (3*STG_BYTES)              // 61440
#define CHUNKS 48

__global__ __launch_bounds__(256, 2) void gemm_ca(
    const float* __restrict__ b0p, const float* __restrict__ b1p,
    const float* __restrict__ b2p,
    float* __restrict__ Out, int mode)
{
    extern __shared__ __align__(16) unsigned smem[];
    const unsigned sbase = smem_u32(smem);

    const float* A  = (mode == 0) ? g_xr : g_attn;
    const float* Bt = (mode == 0) ? g_wT : g_woT;

    const int t    = threadIdx.x;
    const int warp = t >> 5;
    const int lane = t & 31;
    const int g    = lane >> 2;
    const int tg   = lane & 3;
    const int wm   = (warp & 1) * 64;
    const int wn   = (warp >> 1) * 32;
    const int n0   = blockIdx.x * 128;
    const int m0   = blockIdx.y * 128;

    const unsigned a_lane = (((lane >> 3) & 1) * 8 + (lane & 7)) * AST + (lane >> 4) * 4;
    const unsigned b_lane = (lane & 7) * BKST + (lane >> 3) * 4;

    const int arow = t >> 2, aseg = t & 3;
    const float* Ag = A  + (size_t)(m0 + arow) * Esz + aseg * 4;
    const float* Bg = Bt + (size_t)(n0 + arow) * Esz + aseg * 4;
    const unsigned sa_off0 = (arow * AST + aseg * 4) * 4;
    const unsigned sa_off1 = ((arow + 64) * AST + aseg * 4) * 4;
    const unsigned sb_off0 = 128 * AST * 4 + (arow * BKST + aseg * 4) * 4;
    const unsigned sb_off1 = 128 * AST * 4 + ((arow + 64) * BKST + aseg * 4) * 4;

#define GISSUE(chunk, buf) do {                                   \
    unsigned s0 = sbase + (unsigned)(buf) * STG_BYTES;            \
    int c0 = (chunk) * 16;                                        \
    cp16(s0 + sa_off0, Ag + c0);                                  \
    cp16(s0 + sa_off1, Ag + (size_t)64 * Esz + c0);               \
    cp16(s0 + sb_off0, Bg + c0);                                  \
    cp16(s0 + sb_off1, Bg + (size_t)64 * Esz + c0);               \
} while (0)

    GISSUE(0, 0); CP_COMMIT();
    GISSUE(1, 1); CP_COMMIT();

    float acc[4][4][4];
    #pragma unroll
    for (int mi = 0; mi < 4; mi++)
        #pragma unroll
        for (int ni = 0; ni < 4; ni++)
            #pragma unroll
            for (int j = 0; j < 4; j++) acc[mi][ni][j] = 0.f;

    int buf = 0, buf2 = 2;                 // buf = i%3, buf2 = (i+2)%3
    for (int i = 0; i < CHUNKS; i++) {
        CP_WAIT1();
        __syncthreads();
        if (i + 2 < CHUNKS) GISSUE(i + 2, buf2);
        CP_COMMIT();                       // possibly-empty group keeps counts aligned

        const unsigned sA = sbase + (unsigned)buf * STG_BYTES;
        const unsigned sB = sA + 128 * AST * 4;

        unsigned bf[4][4];
        #pragma unroll
        for (int ni = 0; ni < 4; ni++)
            ldsm_x4(bf[ni][0], bf[ni][1], bf[ni][2], bf[ni][3],
                    sB + 4 * ((wn + ni * 8) * BKST + b_lane));
        #pragma unroll
        for (int ks = 0; ks < 2; ks++) {
            unsigned a[4][4];
            #pragma unroll
            for (int mi = 0; mi < 4; mi++)
                ldsm_x4(a[mi][0], a[mi][1], a[mi][2], a[mi][3],
                        sA + 4 * ((wm + mi * 16) * AST + ks * 8 + a_lane));
            #pragma unroll
            for (int ni = 0; ni < 4; ni++)
                #pragma unroll
                for (int mi = 0; mi < 4; mi++)
                    mma_tf32(acc[mi][ni], a[mi], bf[ni][2 * ks], bf[ni][2 * ks + 1]);
        }
        buf  = (buf  == 2) ? 0 : buf + 1;
        buf2 = (buf2 == 2) ? 0 : buf2 + 1;
    }
#undef GISSUE

    // ---- epilogue (identical to R10-proven) ----
    if (mode == 0) {
        const int which = n0 / Esz;
        const float* bias = (which == 0) ? b0p : (which == 1 ? b1p : b2p);
        float* OUTsel     = (which == 0) ? g_q : (which == 1 ? g_k : g_v);
        const float bsc   = (which == 0) ? 0.125f : 1.0f;
        const int nrel = n0 % Esz;
        #pragma unroll
        for (int mi = 0; mi < 4; mi++) {
            const int row_lo = m0 + wm + mi * 16 + g;
            const int row_hi = row_lo + 8;
            const int blo = row_lo >> 10, slo = row_lo & 1023;
            const int bhi = row_hi >> 10, shi = row_hi & 1023;
            #pragma unroll
            for (int ni = 0; ni < 4; ni++) {
                const int nc = nrel + wn + ni * 8 + 2 * tg;
                const int head = nc >> 6, d = nc & 63;
                float2 bb = *(const float2*)(bias + head * Dsz + d);
                bb.x *= bsc; bb.y *= bsc;
                float* olo = OUTsel + ((((size_t)blo * Hsz + head) << 10) + slo) * Dsz + d;
                float* ohi = OUTsel + ((((size_t)bhi * Hsz + head) << 10) + shi) * Dsz + d;
                float2 wlo, whi;
                wlo.x = roundtf(acc[mi][ni][0] + bb.x);
                wlo.y = roundtf(acc[mi][ni][1] + bb.y);
                whi.x = roundtf(acc[mi][ni][2] + bb.x);
                whi.y = roundtf(acc[mi][ni][3] + bb.y);
                *(float2*)olo = wlo;
                *(float2*)ohi = whi;
            }
        }
    } else {
        #pragma unroll
        for (int mi = 0; mi < 4; mi++) {
            const int row_lo = m0 + wm + mi * 16 + g;
            float* olo = Out + (size_t)row_lo * Esz + n0;
            float* ohi = olo + (size_t)8 * Esz;
            #pragma unroll
            for (int ni = 0; ni < 4; ni++) {
                const int col = wn + ni * 8 + 2 * tg;
                float2 bb = *(const float2*)(b0p + n0 + col);
                float2 wlo, whi;
                wlo.x = acc[mi][ni][0] + bb.x; wlo.y = acc[mi][ni][1] + bb.y;
                whi.x = acc[mi][ni][2] + bb.x; whi.y = acc[mi][ni][3] + bb.y;
                *(float2*)(olo + col) = wlo;
                *(float2*)(ohi + col) = whi;
            }
        }
    }
}

// ============================================================================
// Flash attention, Br=128 (8 warps). Per-warp code identical to R10-proven;
// K/V loaded once per 128 query rows (halved reload traffic).
// KP buffer: 128 rows x KST (Q staging -> K rows 0-63 -> P rows 0-127).
// ============================================================================
#define KST 68
#define VST 72
#define ATTN_SMEM (128*KST*4 + 64*VST*4)   // 53248

__global__ __launch_bounds__(256) void attn_kernel()
{
    extern __shared__ __align__(16) unsigned asmem[];
    unsigned* KPsm = asmem;                 // [128][KST]
    unsigned* Vsm  = asmem + 128 * KST;     // [64][VST]

    const int bh = blockIdx.y;
    const int b = bh / Hsz, h = bh % Hsz;
    const int tid  = threadIdx.x;
    const int warp = tid >> 5;
    const int lane = tid & 31;
    const int g  = lane >> 2;
    const int tg = lane & 3;
    const int r0 = warp * 16;              // 0..112

    const unsigned ks_base = smem_u32(KPsm);
    const unsigned kf_lane = (lane & 7) * KST + (lane >> 3) * 4;
    const unsigned pf_lane = (((lane >> 3) & 1) * 8 + (lane & 7)) * KST + (lane >> 4) * 4;

    // ---- stage Q (scaled+rounded) rows 0-127, extract A-frags ----
    {
        const uint4* Qg = (const uint4*)(g_q + ((size_t)bh * Ssz + blockIdx.x * 128) * Dsz);
        #pragma unroll
        for (int i = 0; i < 8; i++) {
            int idx = i * 256 + tid;       // 2048 uint4
            int row = idx >> 4, c = (idx & 15) << 2;
            *(uint4*)&KPsm[row * KST + c] = Qg[idx];
        }
    }
    __syncthreads();

    unsigned qa[8][4];
    #pragma unroll
    for (int kk = 0; kk < 8; kk++) {
        unsigned addr = ks_base + 4 * (r0 * KST + kk * 8 + pf_lane);
        ldsm_x4(qa[kk][0], qa[kk][1], qa[kk][2], qa[kk][3], addr);
    }
    __syncthreads();

    float o[8][4];
    #pragma unroll
    for (int nf = 0; nf < 8; nf++)
        #pragma unroll
        for (int j = 0; j < 4; j++) o[nf][j] = 0.f;
    float m_lo = -1e30f, m_hi = -1e30f, l_lo = 0.f, l_hi = 0.f;

    const uint4* Kg0 = (const uint4*)(g_k + (size_t)bh * (Ssz * Dsz));
    const uint4* Vg0 = (const uint4*)(g_v + (size_t)bh * (Ssz * Dsz));

    for (int kb = 0; kb < Ssz / 64; kb++) {
        const uint4* Kg = Kg0 + kb * 1024;
        const uint4* Vg = Vg0 + kb * 1024;
        #pragma unroll
        for (int i = 0; i < 4; i++) {
            int idx = i * 256 + tid;       // 1024 uint4 per tile
            int row = idx >> 4, c = (idx & 15) << 2;
            *(uint4*)&KPsm[row * KST + c] = Kg[idx];
            *(uint4*)&Vsm[row * VST + c]  = Vg[idx];
        }
        __syncthreads();

        float s[8][4];
        #pragma unroll
        for (int nf = 0; nf < 8; nf++)
            #pragma unroll
            for (int j = 0; j < 4; j++) s[nf][j] = 0.f;

        #pragma unroll
        for (int nf = 0; nf < 8; nf++) {
            #pragma unroll
            for (int p = 0; p < 4; p++) {
                unsigned kb0, kb1, kb2, kb3;
                unsigned addr = ks_base + 4 * ((nf * 8) * KST + p * 16 + kf_lane);
                ldsm_x4(kb0, kb1, kb2, kb3, addr);
                mma_tf32(s[nf], qa[2 * p],     kb0, kb1);
                mma_tf32(s[nf], qa[2 * p + 1], kb2, kb3);
            }
        }
        __syncthreads();                   // all warps done reading K before P overwrite

        float tmax_lo = -1e30f, tmax_hi = -1e30f;
        #pragma unroll
        for (int nf = 0; nf < 8; nf++) {
            tmax_lo = fmaxf(tmax_lo, fmaxf(s[nf][0], s[nf][1]));
            tmax_hi = fmaxf(tmax_hi, fmaxf(s[nf][2], s[nf][3]));
        }
        tmax_lo = fmaxf(tmax_lo, __shfl_xor_sync(0xffffffffu, tmax_lo, 1));
        tmax_lo = fmaxf(tmax_lo, __shfl_xor_sync(0xffffffffu, tmax_lo, 2));
        tmax_hi = fmaxf(tmax_hi, __shfl_xor_sync(0xffffffffu, tmax_hi, 1));
        tmax_hi = fmaxf(tmax_hi, __shfl_xor_sync(0xffffffffu, tmax_hi, 2));

        float mn_lo = fmaxf(m_lo, tmax_lo);
        float mn_hi = fmaxf(m_hi, tmax_hi);
        float a_lo = __expf(m_lo - mn_lo);
        float a_hi = __expf(m_hi - mn_hi);

        float sum_lo = 0.f, sum_hi = 0.f;
        #pragma unroll
        for (int nf = 0; nf < 8; nf++) {
            float p0 = __expf(s[nf][0] - mn_lo);
            float p1 = __expf(s[nf][1] - mn_lo);
            float p2 = __expf(s[nf][2] - mn_hi);
            float p3 = __expf(s[nf][3] - mn_hi);
            sum_lo += p0 + p1;
            sum_hi += p2 + p3;
            uint2 plo, phi;
            plo.x = f2tf(p0); plo.y = f2tf(p1);
            phi.x = f2tf(p2); phi.y = f2tf(p3);
            *(uint2*)&KPsm[(r0 + g) * KST + nf * 8 + 2 * tg]     = plo;
            *(uint2*)&KPsm[(r0 + g + 8) * KST + nf * 8 + 2 * tg] = phi;
            o[nf][0] *= a_lo; o[nf][1] *= a_lo;
            o[nf][2] *= a_hi; o[nf][3] *= a_hi;
        }
        sum_lo += __shfl_xor_sync(0xffffffffu, sum_lo, 1);
        sum_lo += __shfl_xor_sync(0xffffffffu, sum_lo, 2);
        sum_hi += __shfl_xor_sync(0xffffffffu, sum_hi, 1);
        sum_hi += __shfl_xor_sync(0xffffffffu, sum_hi, 2);
        l_lo = l_lo * a_lo + sum_lo;
        l_hi = l_hi * a_hi + sum_hi;
        m_lo = mn_lo; m_hi = mn_hi;
        __syncwarp();                      // P visible within warp

        #pragma unroll
        for (int kk = 0; kk < 8; kk++) {
            unsigned pa[4];
            unsigned addr = ks_base + 4 * (r0 * KST + kk * 8 + pf_lane);
            ldsm_x4(pa[0], pa[1], pa[2], pa[3], addr);
            #pragma unroll
            for (int nf = 0; nf < 8; nf++) {
                unsigned b0 = Vsm[(kk * 8 + tg) * VST + nf * 8 + g];
                unsigned b1 = Vsm[(kk * 8 + tg + 4) * VST + nf * 8 + g];
                mma_tf32(o[nf], pa, b0, b1);
            }
        }
        __syncthreads();                   // done with P & V before next tile
    }

    float inv_lo = 1.f / l_lo;
    float inv_hi = 1.f / l_hi;
    const int qrow_lo = blockIdx.x * 128 + r0 + g;
    float* out_lo = g_attn + ((size_t)b * Ssz + qrow_lo) * Esz + h * Dsz;
    float* out_hi = out_lo + 8 * Esz;
    #pragma unroll
    for (int nf = 0; nf < 8; nf++) {
        int col = nf * 8 + 2 * tg;
        float2 wlo, whi;
        wlo.x = roundtf(o[nf][0] * inv_lo); wlo.y = roundtf(o[nf][1] * inv_lo);
        whi.x = roundtf(o[nf][2] * inv_hi); whi.y = roundtf(o[nf][3] * inv_hi);
        *(float2*)(out_lo + col) = wlo;
        *(float2*)(out_hi + col) = whi;
    }
}

// ---------------- launch ----------------
extern "C" void kernel_launch(void* const* d_in, const int* in_sizes, int n_in,
                              void* d_out, int out_size)
{
    const float* X  = (const float*)d_in[0];
    const float* Wq = (const float*)d_in[1];
    const float* bq = (const float*)d_in[2];
    const float* Wk = (const float*)d_in[3];
    const float* bk = (const float*)d_in[4];
    const float* Wv = (const float*)d_in[5];
    const float* bv = (const float*)d_in[6];
    const float* Wo = (const float*)d_in[7];
    const float* bo = (const float*)d_in[8];
    float* out = (float*)d_out;

    (void)cudaFuncSetAttribute(gemm_ca, cudaFuncAttributeMaxDynamicSharedMemorySize, GSMEM);
    (void)cudaFuncSetAttribute(attn_kernel, cudaFuncAttributeMaxDynamicSharedMemorySize, ATTN_SMEM);

    // one-time rounding / layout conversions
    conv_round<<<(Msz * Esz) / (256 * 4), 256>>>(X);
    conv_wqkvT<<<3 * Esz, 128>>>(Wq, Wk, Wv);
    conv_woT<<<Esz, 128>>>(Wo);

    // QKV projection (tf32 mma + cp.async 3-stage pipeline)
    gemm_ca<<<dim3(18, 64), 256, GSMEM>>>(bq, bk, bv, nullptr, 0);

    // attention (Br=128)
    attn_kernel<<<dim3(Ssz / 128, Bsz * Hsz), 256, ATTN_SMEM>>>();

    // output projection
    gemm_ca<<<dim3(6, 64), 256, GSMEM>>>(bo, nullptr, nullptr, out, 1);
}

// round 12
// speedup vs baseline: 1.1120x; 1.0475x over previous
#include <cuda_runtime.h>
#include <cuda_bf16.h>
#include <cstdint>

#define Bsz 8
#define Ssz 1024
#define Esz 768
#define Hsz 12
#define Dsz 64
#define Msz (Bsz*Ssz)   // 8192

// ---------------- scratch (device globals; referenced ONLY in device code) ----------------
__device__ float g_q[Bsz*Hsz*Ssz*Dsz];     // rounded + 0.125-scaled q
__device__ float g_k[Bsz*Hsz*Ssz*Dsz];     // rounded k
__device__ float g_v[Bsz*Hsz*Ssz*Dsz];     // rounded v
__device__ float g_attn[Bsz*Ssz*Esz];      // rounded attention output
__device__ float g_xr[(size_t)Msz*Esz];    // rounded X
__device__ float g_wT[(size_t)(3*Esz)*Esz];// rounded W^T [2304][768], q rows pre-scaled
__device__ float g_woT[(size_t)Esz*Esz];   // rounded Wo^T [768][768]

// ---------------- helpers ----------------
__device__ __forceinline__ unsigned f2tf(float f) {
    unsigned u;
    asm("cvt.rna.tf32.f32 %0, %1;" : "=r"(u) : "f"(f));
    return u;
}
__device__ __forceinline__ float roundtf(float f) { return __uint_as_float(f2tf(f)); }
__device__ __forceinline__ void mma_tf32(float* c, const unsigned* a, unsigned b0, unsigned b1) {
    asm volatile(
        "mma.sync.aligned.m16n8k8.row.col.f32.tf32.tf32.f32 "
        "{%0,%1,%2,%3}, {%4,%5,%6,%7}, {%8,%9}, {%0,%1,%2,%3};"
        : "+f"(c[0]), "+f"(c[1]), "+f"(c[2]), "+f"(c[3])
        : "r"(a[0]), "r"(a[1]), "r"(a[2]), "r"(a[3]), "r"(b0), "r"(b1));
}
__device__ __forceinline__ void ldsm_x4(unsigned& r0, unsigned& r1, unsigned& r2, unsigned& r3,
                                        unsigned saddr) {
    asm volatile("ldmatrix.sync.aligned.m8n8.x4.shared.b16 {%0,%1,%2,%3}, [%4];"
        : "=r"(r0), "=r"(r1), "=r"(r2), "=r"(r3) : "r"(saddr));
}
__device__ __forceinline__ unsigned smem_u32(const void* p) {
    unsigned a;
    asm("{ .reg .u64 t; cvta.to.shared.u64 t, %1; cvt.u32.u64 %0, t; }" : "=r"(a) : "l"(p));
    return a;
}
__device__ __forceinline__ void cp16(unsigned dst, const float* src) {
    asm volatile("cp.async.cg.shared.global [%0], [%1], 16;" :: "r"(dst), "l"(src));
}
#define CP_COMMIT()  asm volatile("cp.async.commit_group;" ::: "memory")
#define CP_WAIT1()   asm volatile("cp.async.wait_group 1;" ::: "memory")

// ============================================================================
// Conversion kernels (one-time, tiny). Write device globals from device code.
// ============================================================================
__global__ __launch_bounds__(256) void conv_round(const float* __restrict__ src)
{
    int i = (blockIdx.x * 256 + threadIdx.x) * 4;
    float4 v = *(const float4*)(src + i);
    v.x = roundtf(v.x); v.y = roundtf(v.y); v.z = roundtf(v.z); v.w = roundtf(v.w);
    *(float4*)(g_xr + i) = v;
}

__global__ __launch_bounds__(128) void conv_wqkvT(const float* __restrict__ Wq,
                                                  const float* __restrict__ Wk,
                                                  const float* __restrict__ Wv)
{
    int n = blockIdx.x;
    int which = n / Esz, rem = n % Esz, h = rem >> 6, d = rem & 63;
    const float* W = (which == 0) ? Wq : (which == 1 ? Wk : Wv);
    const float sc = (which == 0) ? 0.125f : 1.0f;
    const float* col = W + (size_t)h * Esz * Dsz + d;
    float* row = g_wT + (size_t)n * Esz;
    for (int e = threadIdx.x; e < Esz; e += 128)
        row[e] = roundtf(col[(size_t)e * Dsz] * sc);
}

__global__ __launch_bounds__(128) void conv_woT(const float* __restrict__ Wo)
{
    int n = blockIdx.x;
    float* row = g_woT + (size_t)n * Esz;
    for (int e = threadIdx.x; e < Esz; e += 128)
        row[e] = roundtf(Wo[(size_t)e * Esz + n]);
}

// ============================================================================
// tf32 GEMM, 3-stage cp.async pipeline, Kc=32 (64 MMA per sync).
// Tile 128M x 128N, 8 warps (2m x 4n), warp 64x32, all frags LDSM.
//   mode 0: A=g_xr,   Bt=g_wT   -> qkv epilogue
//   mode 1: A=g_attn, Bt=g_woT  -> oproj epilogue
// ============================================================================
#define AST 36                           // 32 k-words + 4 pad; rows 144B (16B-aligned)
#define BKST 36
#define STG_WORDS (128*AST + 128*BKST)   // 9216
#define STG_BYTES (STG_WORDS*4)          // 36864
#define GSMEM (3*STG_BYTES)              // 110592
#define AOFF  (128*AST*4)                // B area byte offset within a stage
#define CHUNKS 24

__global__ __launch_bounds__(256, 2) void gemm_ca(
    const float* __restrict__ b0p, const float* __restrict__ b1p,
    const float* __restrict__ b2p,
    float* __restrict__ Out, int mode)
{
    extern __shared__ __align__(16) unsigned smem[];
    const unsigned sbase = smem_u32(smem);

    const float* A  = (mode == 0) ? g_xr : g_attn;
    const float* Bt = (mode == 0) ? g_wT : g_woT;

    const int t    = threadIdx.x;
    const int warp = t >> 5;
    const int lane = t & 31;
    const int g    = lane >> 2;
    const int tg   = lane & 3;
    const int wm   = (warp & 1) * 64;
    const int wn   = (warp >> 1) * 32;
    const int n0   = blockIdx.x * 128;
    const int m0   = blockIdx.y * 128;

    const unsigned a_lane = (((lane >> 3) & 1) * 8 + (lane & 7)) * AST + (lane >> 4) * 4;
    const unsigned b_lane = (lane & 7) * BKST + (lane >> 3) * 4;

    // global/smem mapping: 4 (row,seg) pairs per thread; 8 cp16 per chunk
    const int row_ = t >> 3;               // 0..31
    const int seg_ = t & 7;                // 0..7
    const float* AgBase = A  + (size_t)m0 * Esz + seg_ * 4;
    const float* BgBase = Bt + (size_t)n0 * Esz + seg_ * 4;

#define GISSUE(chunk, buf) do {                                               \
    const unsigned s0 = sbase + (unsigned)(buf) * STG_BYTES;                  \
    const int c0 = (chunk) * 32;                                              \
    _Pragma("unroll")                                                         \
    for (int it = 0; it < 4; it++) {                                          \
        const int row = row_ + it * 32;                                       \
        cp16(s0 + (unsigned)(row * AST + seg_ * 4) * 4,                       \
             AgBase + (size_t)row * Esz + c0);                                \
        cp16(s0 + AOFF + (unsigned)(row * BKST + seg_ * 4) * 4,               \
             BgBase + (size_t)row * Esz + c0);                                \
    }                                                                         \
} while (0)

    GISSUE(0, 0); CP_COMMIT();
    GISSUE(1, 1); CP_COMMIT();

    float acc[4][4][4];
    #pragma unroll
    for (int mi = 0; mi < 4; mi++)
        #pragma unroll
        for (int ni = 0; ni < 4; ni++)
            #pragma unroll
            for (int j = 0; j < 4; j++) acc[mi][ni][j] = 0.f;

    int buf = 0, buf2 = 2;                 // buf = i%3, buf2 = (i+2)%3
    for (int i = 0; i < CHUNKS; i++) {
        CP_WAIT1();
        __syncthreads();
        if (i + 2 < CHUNKS) GISSUE(i + 2, buf2);
        CP_COMMIT();                       // possibly-empty group keeps counts aligned

        const unsigned sA = sbase + (unsigned)buf * STG_BYTES;
        const unsigned sB = sA + AOFF;

        #pragma unroll
        for (int ksp = 0; ksp < 2; ksp++) {            // k-pair: words ksp*16..+15
            unsigned bf[4][4];
            #pragma unroll
            for (int ni = 0; ni < 4; ni++)
                ldsm_x4(bf[ni][0], bf[ni][1], bf[ni][2], bf[ni][3],
                        sB + 4 * ((wn + ni * 8) * BKST + ksp * 16 + b_lane));
            #pragma unroll
            for (int ks2 = 0; ks2 < 2; ks2++) {
                const int ks = ksp * 2 + ks2;
                unsigned a[4][4];
                #pragma unroll
                for (int mi = 0; mi < 4; mi++)
                    ldsm_x4(a[mi][0], a[mi][1], a[mi][2], a[mi][3],
                            sA + 4 * ((wm + mi * 16) * AST + ks * 8 + a_lane));
                #pragma unroll
                for (int ni = 0; ni < 4; ni++)
                    #pragma unroll
                    for (int mi = 0; mi < 4; mi++)
                        mma_tf32(acc[mi][ni], a[mi], bf[ni][2 * ks2], bf[ni][2 * ks2 + 1]);
            }
        }
        buf  = (buf  == 2) ? 0 : buf + 1;
        buf2 = (buf2 == 2) ? 0 : buf2 + 1;
    }
#undef GISSUE

    // ---- epilogue (R10/R11-proven) ----
    if (mode == 0) {
        const int which = n0 / Esz;
        const float* bias = (which == 0) ? b0p : (which == 1 ? b1p : b2p);
        float* OUTsel     = (which == 0) ? g_q : (which == 1 ? g_k : g_v);
        const float bsc   = (which == 0) ? 0.125f : 1.0f;
        const int nrel = n0 % Esz;
        #pragma unroll
        for (int mi = 0; mi < 4; mi++) {
            const int row_lo = m0 + wm + mi * 16 + g;
            const int row_hi = row_lo + 8;
            const int blo = row_lo >> 10, slo = row_lo & 1023;
            const int bhi = row_hi >> 10, shi = row_hi & 1023;
            #pragma unroll
            for (int ni = 0; ni < 4; ni++) {
                const int nc = nrel + wn + ni * 8 + 2 * tg;
                const int head = nc >> 6, d = nc & 63;
                float2 bb = *(const float2*)(bias + head * Dsz + d);
                bb.x *= bsc; bb.y *= bsc;
                float* olo = OUTsel + ((((size_t)blo * Hsz + head) << 10) + slo) * Dsz + d;
                float* ohi = OUTsel + ((((size_t)bhi * Hsz + head) << 10) + shi) * Dsz + d;
                float2 wlo, whi;
                wlo.x = roundtf(acc[mi][ni][0] + bb.x);
                wlo.y = roundtf(acc[mi][ni][1] + bb.y);
                whi.x = roundtf(acc[mi][ni][2] + bb.x);
                whi.y = roundtf(acc[mi][ni][3] + bb.y);
                *(float2*)olo = wlo;
                *(float2*)ohi = whi;
            }
        }
    } else {
        #pragma unroll
        for (int mi = 0; mi < 4; mi++) {
            const int row_lo = m0 + wm + mi * 16 + g;
            float* olo = Out + (size_t)row_lo * Esz + n0;
            float* ohi = olo + (size_t)8 * Esz;
            #pragma unroll
            for (int ni = 0; ni < 4; ni++) {
                const int col = wn + ni * 8 + 2 * tg;
                float2 bb = *(const float2*)(b0p + n0 + col);
                float2 wlo, whi;
                wlo.x = acc[mi][ni][0] + bb.x; wlo.y = acc[mi][ni][1] + bb.y;
                whi.x = acc[mi][ni][2] + bb.x; whi.y = acc[mi][ni][3] + bb.y;
                *(float2*)(olo + col) = wlo;
                *(float2*)(ohi + col) = whi;
            }
        }
    }
}

// ============================================================================
// Flash attention, Br=128 (8 warps) — unchanged from R11 (proven).
// ============================================================================
#define KST 68
#define VST 72
#define ATTN_SMEM (128*KST*4 + 64*VST*4)   // 53248

__global__ __launch_bounds__(256) void attn_kernel()
{
    extern __shared__ __align__(16) unsigned asmem[];
    unsigned* KPsm = asmem;                 // [128][KST]
    unsigned* Vsm  = asmem + 128 * KST;     // [64][VST]

    const int bh = blockIdx.y;
    const int b = bh / Hsz, h = bh % Hsz;
    const int tid  = threadIdx.x;
    const int warp = tid >> 5;
    const int lane = tid & 31;
    const int g  = lane >> 2;
    const int tg = lane & 3;
    const int r0 = warp * 16;

    const unsigned ks_base = smem_u32(KPsm);
    const unsigned kf_lane = (lane & 7) * KST + (lane >> 3) * 4;
    const unsigned pf_lane = (((lane >> 3) & 1) * 8 + (lane & 7)) * KST + (lane >> 4) * 4;

    {
        const uint4* Qg = (const uint4*)(g_q + ((size_t)bh * Ssz + blockIdx.x * 128) * Dsz);
        #pragma unroll
        for (int i = 0; i < 8; i++) {
            int idx = i * 256 + tid;
            int row = idx >> 4, c = (idx & 15) << 2;
            *(uint4*)&KPsm[row * KST + c] = Qg[idx];
        }
    }
    __syncthreads();

    unsigned qa[8][4];
    #pragma unroll
    for (int kk = 0; kk < 8; kk++) {
        unsigned addr = ks_base + 4 * (r0 * KST + kk * 8 + pf_lane);
        ldsm_x4(qa[kk][0], qa[kk][1], qa[kk][2], qa[kk][3], addr);
    }
    __syncthreads();

    float o[8][4];
    #pragma unroll
    for (int nf = 0; nf < 8; nf++)
        #pragma unroll
        for (int j = 0; j < 4; j++) o[nf][j] = 0.f;
    float m_lo = -1e30f, m_hi = -1e30f, l_lo = 0.f, l_hi = 0.f;

    const uint4* Kg0 = (const uint4*)(g_k + (size_t)bh * (Ssz * Dsz));
    const uint4* Vg0 = (const uint4*)(g_v + (size_t)bh * (Ssz * Dsz));

    for (int kb = 0; kb < Ssz / 64; kb++) {
        const uint4* Kg = Kg0 + kb * 1024;
        const uint4* Vg = Vg0 + kb * 1024;
        #pragma unroll
        for (int i = 0; i < 4; i++) {
            int idx = i * 256 + tid;
            int row = idx >> 4, c = (idx & 15) << 2;
            *(uint4*)&KPsm[row * KST + c] = Kg[idx];
            *(uint4*)&Vsm[row * VST + c]  = Vg[idx];
        }
        __syncthreads();

        float s[8][4];
        #pragma unroll
        for (int nf = 0; nf < 8; nf++)
            #pragma unroll
            for (int j = 0; j < 4; j++) s[nf][j] = 0.f;

        #pragma unroll
        for (int nf = 0; nf < 8; nf++) {
            #pragma unroll
            for (int p = 0; p < 4; p++) {
                unsigned kb0, kb1, kb2, kb3;
                unsigned addr = ks_base + 4 * ((nf * 8) * KST + p * 16 + kf_lane);
                ldsm_x4(kb0, kb1, kb2, kb3, addr);
                mma_tf32(s[nf], qa[2 * p],     kb0, kb1);
                mma_tf32(s[nf], qa[2 * p + 1], kb2, kb3);
            }
        }
        __syncthreads();

        float tmax_lo = -1e30f, tmax_hi = -1e30f;
        #pragma unroll
        for (int nf = 0; nf < 8; nf++) {
            tmax_lo = fmaxf(tmax_lo, fmaxf(s[nf][0], s[nf][1]));
            tmax_hi = fmaxf(tmax_hi, fmaxf(s[nf][2], s[nf][3]));
        }
        tmax_lo = fmaxf(tmax_lo, __shfl_xor_sync(0xffffffffu, tmax_lo, 1));
        tmax_lo = fmaxf(tmax_lo, __shfl_xor_sync(0xffffffffu, tmax_lo, 2));
        tmax_hi = fmaxf(tmax_hi, __shfl_xor_sync(0xffffffffu, tmax_hi, 1));
        tmax_hi = fmaxf(tmax_hi, __shfl_xor_sync(0xffffffffu, tmax_hi, 2));

        float mn_lo = fmaxf(m_lo, tmax_lo);
        float mn_hi = fmaxf(m_hi, tmax_hi);
        float a_lo = __expf(m_lo - mn_lo);
        float a_hi = __expf(m_hi - mn_hi);

        float sum_lo = 0.f, sum_hi = 0.f;
        #pragma unroll
        for (int nf = 0; nf < 8; nf++) {
            float p0 = __expf(s[nf][0] - mn_lo);
            float p1 = __expf(s[nf][1] - mn_lo);
            float p2 = __expf(s[nf][2] - mn_hi);
            float p3 = __expf(s[nf][3] - mn_hi);
            sum_lo += p0 + p1;
            sum_hi += p2 + p3;
            uint2 plo, phi;
            plo.x = f2tf(p0); plo.y = f2tf(p1);
            phi.x = f2tf(p2); phi.y = f2tf(p3);
            *(uint2*)&KPsm[(r0 + g) * KST + nf * 8 + 2 * tg]     = plo;
            *(uint2*)&KPsm[(r0 + g + 8) * KST + nf * 8 + 2 * tg] = phi;
            o[nf][0] *= a_lo; o[nf][1] *= a_lo;
            o[nf][2] *= a_hi; o[nf][3] *= a_hi;
        }
        sum_lo += __shfl_xor_sync(0xffffffffu, sum_lo, 1);
        sum_lo += __shfl_xor_sync(0xffffffffu, sum_lo, 2);
        sum_hi += __shfl_xor_sync(0xffffffffu, sum_hi, 1);
        sum_hi += __shfl_xor_sync(0xffffffffu, sum_hi, 2);
        l_lo = l_lo * a_lo + sum_lo;
        l_hi = l_hi * a_hi + sum_hi;
        m_lo = mn_lo; m_hi = mn_hi;
        __syncwarp();

        #pragma unroll
        for (int kk = 0; kk < 8; kk++) {
            unsigned pa[4];
            unsigned addr = ks_base + 4 * (r0 * KST + kk * 8 + pf_lane);
            ldsm_x4(pa[0], pa[1], pa[2], pa[3], addr);
            #pragma unroll
            for (int nf = 0; nf < 8; nf++) {
                unsigned b0 = Vsm[(kk * 8 + tg) * VST + nf * 8 + g];
                unsigned b1 = Vsm[(kk * 8 + tg + 4) * VST + nf * 8 + g];
                mma_tf32(o[nf], pa, b0, b1);
            }
        }
        __syncthreads();
    }

    float inv_lo = 1.f / l_lo;
    float inv_hi = 1.f / l_hi;
    const int qrow_lo = blockIdx.x * 128 + r0 + g;
    float* out_lo = g_attn + ((size_t)b * Ssz + qrow_lo) * Esz + h * Dsz;
    float* out_hi = out_lo + 8 * Esz;
    #pragma unroll
    for (int nf = 0; nf < 8; nf++) {
        int col = nf * 8 + 2 * tg;
        float2 wlo, whi;
        wlo.x = roundtf(o[nf][0] * inv_lo); wlo.y = roundtf(o[nf][1] * inv_lo);
        whi.x = roundtf(o[nf][2] * inv_hi); whi.y = roundtf(o[nf][3] * inv_hi);
        *(float2*)(out_lo + col) = wlo;
        *(float2*)(out_hi + col) = whi;
    }
}

// ---------------- launch ----------------
extern "C" void kernel_launch(void* const* d_in, const int* in_sizes, int n_in,
                              void* d_out, int out_size)
{
    const float* X  = (const float*)d_in[0];
    const float* Wq = (const float*)d_in[1];
    const float* bq = (const float*)d_in[2];
    const float* Wk = (const float*)d_in[3];
    const float* bk = (const float*)d_in[4];
    const float* Wv = (const float*)d_in[5];
    const float* bv = (const float*)d_in[6];
    const float* Wo = (const float*)d_in[7];
    const float* bo = (const float*)d_in[8];
    float* out = (float*)d_out;

    (void)cudaFuncSetAttribute(gemm_ca, cudaFuncAttributeMaxDynamicSharedMemorySize, GSMEM);
    (void)cudaFuncSetAttribute(attn_kernel, cudaFuncAttributeMaxDynamicSharedMemorySize, ATTN_SMEM);

    // one-time rounding / layout conversions
    conv_round<<<(Msz * Esz) / (256 * 4), 256>>>(X);
    conv_wqkvT<<<3 * Esz, 128>>>(Wq, Wk, Wv);
    conv_woT<<<Esz, 128>>>(Wo);

    // QKV projection (tf32 mma + cp.async 3-stage pipeline, Kc=32)
    gemm_ca<<<dim3(18, 64), 256, GSMEM>>>(bq, bk, bv, nullptr, 0);

    // attention (Br=128)
    attn_kernel<<<dim3(Ssz / 128, Bsz * Hsz), 256, ATTN_SMEM>>>();

    // output projection
    gemm_ca<<<dim3(6, 64), 256, GSMEM>>>(bo, nullptr, nullptr, out, 1);
}